// round 11
// baseline (speedup 1.0000x reference)
#include <cuda_runtime.h>
#include <cstdint>

// ============================================================
// RSNN: out = LIF16(x @ W^T + b)/16,  M=32768, N=512, K=512 fp32
// Bit-exact fp32 GEMM (k-sequential FMA == reference rounding) on
// the FFMA2 pipe, cp.async 3-stage pipeline, 2 CTAs/SM.
// R11: BM 128->64 (grid 2048) to cut wave-quantization tail loss
// from ~16% to ~4%.
// ============================================================

typedef unsigned int u32;
typedef unsigned long long ull;

#define KD 512
#define ND 512
#define MAXM 32768

__device__ float g_xt[(size_t)KD * MAXM];       // 64 MB  XT[k][m]
__device__ float g_wd[(size_t)KD * 2 * ND];     // 2 MB   WD[k][2n] (dup pairs)

#define SWZ(off) ((off) ^ (((off) >> 3) & 0x70))

__device__ __forceinline__ u32 smem_u32(const void* p) {
    u32 a;
    asm("{ .reg .u64 t; cvta.to.shared.u64 t, %1; cvt.u32.u64 %0, t; }" : "=r"(a) : "l"(p));
    return a;
}
__device__ __forceinline__ void cpa16(u32 dst, const float* src) {
    asm volatile("cp.async.cg.shared.global [%0], [%1], 16;" :: "r"(dst), "l"(src));
}
#define CP_COMMIT()  asm volatile("cp.async.commit_group;" ::: "memory")
#define CP_WAIT1()   asm volatile("cp.async.wait_group 1;" ::: "memory")
#define CP_WAIT0()   asm volatile("cp.async.wait_group 0;" ::: "memory")

__device__ __forceinline__ void ffma2(ull& d, ull a, ull b) {
    asm("fma.rn.f32x2 %0, %1, %2, %3;" : "=l"(d) : "l"(a), "l"(b), "l"(d));
}
__device__ __forceinline__ void unpack2(ull v, float& lo, float& hi) {
    u32 l, h;
    asm("mov.b64 {%0, %1}, %2;" : "=r"(l), "=r"(h) : "l"(v));
    lo = __uint_as_float(l);
    hi = __uint_as_float(h);
}

// LIF: identical fp ops to reference per step
__device__ __forceinline__ float lif16(float cur) {
    float v = 0.0f, cnt = 0.0f;
#pragma unroll
    for (int t = 0; t < 16; t++) {
        v = fmaf(cur - v, 0.5f, v);
        if (v >= 1.0f) { cnt += 1.0f; v = 0.0f; }
    }
    return cnt * 0.0625f;
}

// ---------------- pre-pass 1: XT[k][m] = X[m][k] ----------------
__global__ void transpose_x(const float* __restrict__ X, int M, int K) {
    __shared__ float t[32][33];
    const int kb = blockIdx.x * 32, mb = blockIdx.y * 32;
    const int tx = threadIdx.x, ty = threadIdx.y;   // 32 x 8
#pragma unroll
    for (int i = 0; i < 4; i++)
        t[ty + 8 * i][tx] = X[(size_t)(mb + ty + 8 * i) * K + kb + tx];
    __syncthreads();
#pragma unroll
    for (int i = 0; i < 4; i++)
        g_xt[(size_t)(kb + ty + 8 * i) * M + mb + tx] = t[tx][ty + 8 * i];
}

// ---------------- pre-pass 2: WD[k][2n..2n+1] = W[n][k] ----------------
__global__ void dup_w(const float* __restrict__ W, int N, int K) {
    int idx = blockIdx.x * 256 + threadIdx.x;     // n*K + k
    if (idx >= N * K) return;
    int n = idx / K, k = idx - n * K;
    float v = W[idx];
    float2 p = {v, v};
    *reinterpret_cast<float2*>(&g_wd[(size_t)k * 2 * N + 2 * n]) = p;
}

// ---------------- GEMM + LIF ----------------
#define BM 64
#define BN 128
#define BK 16
#define NST 3
#define A_ST (BK * BM * 4)          // 4096  (A stage: [k][m], rows 256B)
#define B_ST (BK * BN * 2 * 4)      // 16384 (B stage: [k][2n] swizzled, rows 1024B)
#define STAGE (A_ST + B_ST)         // 20480
#define SM_TOTAL (NST * STAGE)      // 61440

__global__ void __launch_bounds__(256, 2)
gemm_lif(const float* __restrict__ bias, float* __restrict__ out, int M) {
    extern __shared__ char smem[];
    const u32 sb = smem_u32(smem);
    const int tid = threadIdx.x;
    const int n0 = blockIdx.x * BN;     // n fastest -> A tile shared in L2 by 4 CTAs
    const int m0 = blockIdx.y * BM;

    // loader: A 1 unit/thread (row tid>>4, unit tid&15);
    //         B 4 units/thread (rows tid>>6, +4, +8, +12)
    const u32 adst = (tid >> 4) * 256 + (tid & 15) * 16;
    const u32 bdst = A_ST + (tid >> 6) * 1024 + SWZ((tid & 63) * 16);
    const float* ai = g_xt + (size_t)(tid >> 4) * M + m0 + (tid & 15) * 4;
    const float* bi = g_wd + (size_t)(tid >> 6) * (2 * ND) + n0 * 2 + (tid & 63) * 4;

    const int NCHUNK = KD / BK;                  // 32

    // prologue: stages 0,1
#pragma unroll
    for (int c = 0; c < 2; c++) {
        u32 s = sb + c * STAGE;
        cpa16(s + adst,         ai);
        cpa16(s + bdst,         bi);
        cpa16(s + bdst + 4096,  bi + 4 * 2 * ND);
        cpa16(s + bdst + 8192,  bi + 8 * 2 * ND);
        cpa16(s + bdst + 12288, bi + 12 * 2 * ND);
        CP_COMMIT();
        ai += (size_t)BK * M;
        bi += BK * 2 * ND;
    }

    ull acc[2][8];
#pragma unroll
    for (int i = 0; i < 2; i++)
#pragma unroll
        for (int j = 0; j < 8; j++) acc[i][j] = 0ull;

    const int ty = tid >> 4;            // m: 16 x 4 = 64
    const int tx = tid & 15;            // n: 16 x 8 = 128

    for (int c = 0; c < NCHUNK; c++) {
        if (c >= NCHUNK - 2) CP_WAIT0(); else CP_WAIT1();
        __syncthreads();

        // issue chunk c+2 into buffer (c+2)%3 (its last readers synced above)
        if (c + 2 < NCHUNK) {
            u32 s = sb + ((c + 2) % NST) * STAGE;
            cpa16(s + adst,         ai);
            cpa16(s + bdst,         bi);
            cpa16(s + bdst + 4096,  bi + 4 * 2 * ND);
            cpa16(s + bdst + 8192,  bi + 8 * 2 * ND);
            cpa16(s + bdst + 12288, bi + 12 * 2 * ND);
            CP_COMMIT();
            ai += (size_t)BK * M;
            bi += BK * 2 * ND;
        }

        const char* st = smem + (c % NST) * STAGE;
#pragma unroll
        for (int k = 0; k < BK; k++) {
            union { float4 v; ull u[2]; } a0, bq;
            a0.v = *reinterpret_cast<const float4*>(st + k * 256 + ty * 16);
            ull ap[2] = { a0.u[0], a0.u[1] };

            const char* bbase = st + A_ST + k * 1024;
#pragma unroll
            for (int h = 0; h < 2; h++) {
                ull bp[4];
                u32 o0 = tx * 64 + h * 32;
                bq.v = *reinterpret_cast<const float4*>(bbase + SWZ(o0));
                bp[0] = bq.u[0]; bp[1] = bq.u[1];
                bq.v = *reinterpret_cast<const float4*>(bbase + SWZ(o0 + 16));
                bp[2] = bq.u[0]; bp[3] = bq.u[1];
#pragma unroll
                for (int i = 0; i < 2; i++)
#pragma unroll
                    for (int j = 0; j < 4; j++)
                        ffma2(acc[i][h * 4 + j], ap[i], bp[j]);
            }
        }
    }

    // ---- epilogue: bias + LIF + store ----
    float4 bq0 = *reinterpret_cast<const float4*>(bias + n0 + tx * 8);
    float4 bq1 = *reinterpret_cast<const float4*>(bias + n0 + tx * 8 + 4);
    const float bv[8] = { bq0.x, bq0.y, bq0.z, bq0.w, bq1.x, bq1.y, bq1.z, bq1.w };

#pragma unroll
    for (int i = 0; i < 2; i++) {
        float lo[8], hi[8];
#pragma unroll
        for (int j = 0; j < 8; j++) unpack2(acc[i][j], lo[j], hi[j]);

        int m_lo = m0 + ty * 4 + 2 * i;
        float* p0 = out + (size_t)m_lo * ND + n0 + tx * 8;
        float* p1 = p0 + ND;

        float4 o;
        o.x = lif16(lo[0] + bv[0]); o.y = lif16(lo[1] + bv[1]);
        o.z = lif16(lo[2] + bv[2]); o.w = lif16(lo[3] + bv[3]);
        *reinterpret_cast<float4*>(p0) = o;
        o.x = lif16(lo[4] + bv[4]); o.y = lif16(lo[5] + bv[5]);
        o.z = lif16(lo[6] + bv[6]); o.w = lif16(lo[7] + bv[7]);
        *reinterpret_cast<float4*>(p0 + 4) = o;
        o.x = lif16(hi[0] + bv[0]); o.y = lif16(hi[1] + bv[1]);
        o.z = lif16(hi[2] + bv[2]); o.w = lif16(hi[3] + bv[3]);
        *reinterpret_cast<float4*>(p1) = o;
        o.x = lif16(hi[4] + bv[4]); o.y = lif16(hi[5] + bv[5]);
        o.z = lif16(hi[6] + bv[6]); o.w = lif16(hi[7] + bv[7]);
        *reinterpret_cast<float4*>(p1 + 4) = o;
    }
}

extern "C" void kernel_launch(void* const* d_in, const int* in_sizes, int n_in,
                              void* d_out, int out_size) {
    const float* x = (const float*)d_in[0];
    const float* W = (const float*)d_in[1];
    const float* b = (const float*)d_in[2];
    float* out = (float*)d_out;

    const int N = in_sizes[2];          // 512
    const int K = in_sizes[1] / N;      // 512
    const int M = in_sizes[0] / K;      // 32768

    dim3 tb(32, 8);
    dim3 tg(K / 32, M / 32);
    transpose_x<<<tg, tb>>>(x, M, K);
    dup_w<<<(N * K + 255) / 256, 256>>>(W, N, K);

    cudaFuncSetAttribute(gemm_lif, cudaFuncAttributeMaxDynamicSharedMemorySize, SM_TOTAL);
    dim3 grid(N / BN, M / BM);
    gemm_lif<<<grid, 256, SM_TOTAL>>>(b, out, M);
}

// round 14
// speedup vs baseline: 1.5706x; 1.5706x over previous
#include <cuda_runtime.h>
#include <cstdint>

// ============================================================
// RSNN: out = LIF16(x @ W^T + b)/16,  M=32768, N=512, K=512 fp32
// Bit-exact fp32 GEMM (k-sequential FMA == reference rounding) on
// the FFMA2 pipe. R12: 64x128 tile @128 threads (keeps 64 outputs
// /thread = R10 crossbar ratio), 4 CTAs/SM, NST=2 double buffer,
// finer wave tail. Inner loop identical to the 402us R10 kernel.
// ============================================================

typedef unsigned int u32;
typedef unsigned long long ull;

#define KD 512
#define ND 512
#define MAXM 32768

__device__ float g_xt[(size_t)KD * MAXM];       // 64 MB  XT[k][m]
__device__ float g_wd[(size_t)KD * 2 * ND];     // 2 MB   WD[k][2n] (dup pairs)

#define SWZ(off) ((off) ^ (((off) >> 3) & 0x70))

__device__ __forceinline__ u32 smem_u32(const void* p) {
    u32 a;
    asm("{ .reg .u64 t; cvta.to.shared.u64 t, %1; cvt.u32.u64 %0, t; }" : "=r"(a) : "l"(p));
    return a;
}
__device__ __forceinline__ void cpa16(u32 dst, const float* src) {
    asm volatile("cp.async.cg.shared.global [%0], [%1], 16;" :: "r"(dst), "l"(src));
}
#define CP_COMMIT()  asm volatile("cp.async.commit_group;" ::: "memory")
#define CP_WAIT0()   asm volatile("cp.async.wait_group 0;" ::: "memory")

__device__ __forceinline__ void ffma2(ull& d, ull a, ull b) {
    asm("fma.rn.f32x2 %0, %1, %2, %3;" : "=l"(d) : "l"(a), "l"(b), "l"(d));
}
__device__ __forceinline__ void unpack2(ull v, float& lo, float& hi) {
    u32 l, h;
    asm("mov.b64 {%0, %1}, %2;" : "=r"(l), "=r"(h) : "l"(v));
    lo = __uint_as_float(l);
    hi = __uint_as_float(h);
}

// LIF: identical fp ops to reference per step
__device__ __forceinline__ float lif16(float cur) {
    float v = 0.0f, cnt = 0.0f;
#pragma unroll
    for (int t = 0; t < 16; t++) {
        v = fmaf(cur - v, 0.5f, v);
        if (v >= 1.0f) { cnt += 1.0f; v = 0.0f; }
    }
    return cnt * 0.0625f;
}

// ---------------- pre-pass 1: XT[k][m] = X[m][k] ----------------
__global__ void transpose_x(const float* __restrict__ X, int M, int K) {
    __shared__ float t[32][33];
    const int kb = blockIdx.x * 32, mb = blockIdx.y * 32;
    const int tx = threadIdx.x, ty = threadIdx.y;   // 32 x 8
#pragma unroll
    for (int i = 0; i < 4; i++)
        t[ty + 8 * i][tx] = X[(size_t)(mb + ty + 8 * i) * K + kb + tx];
    __syncthreads();
#pragma unroll
    for (int i = 0; i < 4; i++)
        g_xt[(size_t)(kb + ty + 8 * i) * M + mb + tx] = t[tx][ty + 8 * i];
}

// ---------------- pre-pass 2: WD[k][2n..2n+1] = W[n][k] ----------------
__global__ void dup_w(const float* __restrict__ W, int N, int K) {
    int idx = blockIdx.x * 256 + threadIdx.x;     // n*K + k
    if (idx >= N * K) return;
    int n = idx / K, k = idx - n * K;
    float v = W[idx];
    float2 p = {v, v};
    *reinterpret_cast<float2*>(&g_wd[(size_t)k * 2 * N + 2 * n]) = p;
}

// ---------------- GEMM + LIF ----------------
#define BM 64
#define BN 128
#define BK 16
#define NST 2
#define A_ST (BK * BM * 4)          // 4096  (A stage: [k][m], rows 256B)
#define B_ST (BK * BN * 2 * 4)      // 16384 (B stage: [k][2n] swizzled, rows 1024B)
#define STAGE (A_ST + B_ST)         // 20480
#define SM_TOTAL (NST * STAGE)      // 40960

__global__ void __launch_bounds__(128, 4)
gemm_lif(const float* __restrict__ bias, float* __restrict__ out, int M) {
    extern __shared__ char smem[];
    const u32 sb = smem_u32(smem);
    const int tid = threadIdx.x;
    const int n0 = blockIdx.x * BN;     // n fastest -> A tile shared in L2 by 4 CTAs
    const int m0 = blockIdx.y * BM;

    // loaders (128 threads):
    // A: 256 units, 2/thread: rows (tid>>4), (tid>>4)+8 ; 16 units/row
    // B: 1024 units, 8/thread: rows (tid>>6) + 2r, r=0..7 ; 64 units/row
    const u32 adst = (tid >> 4) * 256 + (tid & 15) * 16;
    const u32 bdst = A_ST + (tid >> 6) * 1024 + SWZ((tid & 63) * 16);
    const float* ai = g_xt + (size_t)(tid >> 4) * M + m0 + (tid & 15) * 4;
    const float* bi = g_wd + (size_t)(tid >> 6) * (2 * ND) + n0 * 2 + (tid & 63) * 4;
    const size_t m8 = (size_t)8 * M;

    const int NCHUNK = KD / BK;                  // 32

    // prologue: stage 0 (double buffer, prefetch depth 1)
    {
        u32 s = sb;
        cpa16(s + adst,        ai);
        cpa16(s + adst + 2048, ai + m8);
#pragma unroll
        for (int r = 0; r < 8; r++)
            cpa16(s + bdst + r * 2048, bi + r * 2 * (2 * ND));
        CP_COMMIT();
        ai += (size_t)BK * M;
        bi += BK * 2 * ND;
    }

    ull acc[4][8];
#pragma unroll
    for (int i = 0; i < 4; i++)
#pragma unroll
        for (int j = 0; j < 8; j++) acc[i][j] = 0ull;

    const int ty = tid >> 4;            // m: 8 x 8 = 64
    const int tx = tid & 15;            // n: 16 x 8 = 128

    for (int c = 0; c < NCHUNK; c++) {
        CP_WAIT0();
        __syncthreads();

        // issue chunk c+1 into the other buffer (its readers synced above)
        if (c + 1 < NCHUNK) {
            u32 s = sb + ((c + 1) & 1) * STAGE;
            cpa16(s + adst,        ai);
            cpa16(s + adst + 2048, ai + m8);
#pragma unroll
            for (int r = 0; r < 8; r++)
                cpa16(s + bdst + r * 2048, bi + r * 2 * (2 * ND));
            CP_COMMIT();
            ai += (size_t)BK * M;
            bi += BK * 2 * ND;
        }

        const char* st = smem + (c & 1) * STAGE;
#pragma unroll
        for (int k = 0; k < BK; k++) {
            union { float4 v; ull u[2]; } a0, a1, bq;
            a0.v = *reinterpret_cast<const float4*>(st + k * 256 + ty * 32);
            a1.v = *reinterpret_cast<const float4*>(st + k * 256 + ty * 32 + 16);
            ull ap[4] = { a0.u[0], a0.u[1], a1.u[0], a1.u[1] };

            const char* bbase = st + A_ST + k * 1024;
#pragma unroll
            for (int h = 0; h < 2; h++) {
                ull bp[4];
                u32 o0 = tx * 64 + h * 32;
                bq.v = *reinterpret_cast<const float4*>(bbase + SWZ(o0));
                bp[0] = bq.u[0]; bp[1] = bq.u[1];
                bq.v = *reinterpret_cast<const float4*>(bbase + SWZ(o0 + 16));
                bp[2] = bq.u[0]; bp[3] = bq.u[1];
#pragma unroll
                for (int i = 0; i < 4; i++)
#pragma unroll
                    for (int j = 0; j < 4; j++)
                        ffma2(acc[i][h * 4 + j], ap[i], bp[j]);
            }
        }
    }

    // ---- epilogue: bias + LIF + store ----
    float4 bq0 = *reinterpret_cast<const float4*>(bias + n0 + tx * 8);
    float4 bq1 = *reinterpret_cast<const float4*>(bias + n0 + tx * 8 + 4);
    const float bv[8] = { bq0.x, bq0.y, bq0.z, bq0.w, bq1.x, bq1.y, bq1.z, bq1.w };

#pragma unroll
    for (int i = 0; i < 4; i++) {
        float lo[8], hi[8];
#pragma unroll
        for (int j = 0; j < 8; j++) unpack2(acc[i][j], lo[j], hi[j]);

        int m_lo = m0 + ty * 8 + 2 * i;
        float* p0 = out + (size_t)m_lo * ND + n0 + tx * 8;
        float* p1 = p0 + ND;

        float4 o;
        o.x = lif16(lo[0] + bv[0]); o.y = lif16(lo[1] + bv[1]);
        o.z = lif16(lo[2] + bv[2]); o.w = lif16(lo[3] + bv[3]);
        *reinterpret_cast<float4*>(p0) = o;
        o.x = lif16(lo[4] + bv[4]); o.y = lif16(lo[5] + bv[5]);
        o.z = lif16(lo[6] + bv[6]); o.w = lif16(lo[7] + bv[7]);
        *reinterpret_cast<float4*>(p0 + 4) = o;
        o.x = lif16(hi[0] + bv[0]); o.y = lif16(hi[1] + bv[1]);
        o.z = lif16(hi[2] + bv[2]); o.w = lif16(hi[3] + bv[3]);
        *reinterpret_cast<float4*>(p1) = o;
        o.x = lif16(hi[4] + bv[4]); o.y = lif16(hi[5] + bv[5]);
        o.z = lif16(hi[6] + bv[6]); o.w = lif16(hi[7] + bv[7]);
        *reinterpret_cast<float4*>(p1 + 4) = o;
    }
}

extern "C" void kernel_launch(void* const* d_in, const int* in_sizes, int n_in,
                              void* d_out, int out_size) {
    const float* x = (const float*)d_in[0];
    const float* W = (const float*)d_in[1];
    const float* b = (const float*)d_in[2];
    float* out = (float*)d_out;

    const int N = in_sizes[2];          // 512
    const int K = in_sizes[1] / N;      // 512
    const int M = in_sizes[0] / K;      // 32768

    dim3 tb(32, 8);
    dim3 tg(K / 32, M / 32);
    transpose_x<<<tg, tb>>>(x, M, K);
    dup_w<<<(N * K + 255) / 256, 256>>>(W, N, K);

    cudaFuncSetAttribute(gemm_lif, cudaFuncAttributeMaxDynamicSharedMemorySize, SM_TOTAL);
    dim3 grid(N / BN, M / BM);
    gemm_lif<<<grid, 128, SM_TOTAL>>>(b, out, M);
}

// round 15
// speedup vs baseline: 1.7360x; 1.1053x over previous
#include <cuda_runtime.h>
#include <cstdint>

// ============================================================
// RSNN: out = LIF16(x @ W^T + b)/16,  M=32768, N=512, K=512 fp32
// Bit-exact fp32 GEMM (k-sequential FMA == reference rounding) on
// the FFMA2 pipe. R15: un-duplicated B (WT[k][n] + reg pack_dup),
// BK=32, NST=2, 64x128 @128thr, 4 CTAs/SM. Crossbar demand drops
// ~2x, barriers halve, B global traffic halves.
// ============================================================

typedef unsigned int u32;
typedef unsigned long long ull;

#define KD 512
#define ND 512
#define MAXM 32768

__device__ float g_xt[(size_t)KD * MAXM];       // 64 MB  XT[k][m]
__device__ float g_wt[(size_t)KD * ND];         // 1 MB   WT[k][n]

__device__ __forceinline__ u32 smem_u32(const void* p) {
    u32 a;
    asm("{ .reg .u64 t; cvta.to.shared.u64 t, %1; cvt.u32.u64 %0, t; }" : "=r"(a) : "l"(p));
    return a;
}
__device__ __forceinline__ void cpa16(u32 dst, const float* src) {
    asm volatile("cp.async.cg.shared.global [%0], [%1], 16;" :: "r"(dst), "l"(src));
}
#define CP_COMMIT()  asm volatile("cp.async.commit_group;" ::: "memory")
#define CP_WAIT0()   asm volatile("cp.async.wait_group 0;" ::: "memory")

__device__ __forceinline__ void ffma2(ull& d, ull a, ull b) {
    asm("fma.rn.f32x2 %0, %1, %2, %3;" : "=l"(d) : "l"(a), "l"(b), "l"(d));
}
__device__ __forceinline__ ull pack_dup(float x) {
    ull r;
    u32 u = __float_as_uint(x);
    asm("mov.b64 %0, {%1, %1};" : "=l"(r) : "r"(u));
    return r;
}
__device__ __forceinline__ void unpack2(ull v, float& lo, float& hi) {
    u32 l, h;
    asm("mov.b64 {%0, %1}, %2;" : "=r"(l), "=r"(h) : "l"(v));
    lo = __uint_as_float(l);
    hi = __uint_as_float(h);
}

// LIF: identical fp ops to reference per step
__device__ __forceinline__ float lif16(float cur) {
    float v = 0.0f, cnt = 0.0f;
#pragma unroll
    for (int t = 0; t < 16; t++) {
        v = fmaf(cur - v, 0.5f, v);
        if (v >= 1.0f) { cnt += 1.0f; v = 0.0f; }
    }
    return cnt * 0.0625f;
}

// ---------------- pre-pass 1: XT[k][m] = X[m][k] ----------------
__global__ void transpose_x(const float* __restrict__ X, int M, int K) {
    __shared__ float t[32][33];
    const int kb = blockIdx.x * 32, mb = blockIdx.y * 32;
    const int tx = threadIdx.x, ty = threadIdx.y;   // 32 x 8
#pragma unroll
    for (int i = 0; i < 4; i++)
        t[ty + 8 * i][tx] = X[(size_t)(mb + ty + 8 * i) * K + kb + tx];
    __syncthreads();
#pragma unroll
    for (int i = 0; i < 4; i++)
        g_xt[(size_t)(kb + ty + 8 * i) * M + mb + tx] = t[tx][ty + 8 * i];
}

// ---------------- pre-pass 2: WT[k][n] = W[n][k] ----------------
__global__ void transpose_w(const float* __restrict__ W, int N, int K) {
    __shared__ float t[32][33];
    const int kb = blockIdx.x * 32, nb = blockIdx.y * 32;
    const int tx = threadIdx.x, ty = threadIdx.y;   // 32 x 8
#pragma unroll
    for (int i = 0; i < 4; i++)
        t[ty + 8 * i][tx] = W[(size_t)(nb + ty + 8 * i) * K + kb + tx];
    __syncthreads();
#pragma unroll
    for (int i = 0; i < 4; i++)
        g_wt[(size_t)(kb + ty + 8 * i) * N + nb + tx] = t[tx][ty + 8 * i];
}

// ---------------- GEMM + LIF ----------------
#define BM 64
#define BN 128
#define BK 32
#define NST 2
#define A_ST (BK * BM * 4)          // 8192  (A stage: [k][m], rows 256B)
#define B_ST (BK * BN * 4)          // 16384 (B stage: [k][n], rows 512B)
#define STAGE (A_ST + B_ST)         // 24576
#define SM_TOTAL (NST * STAGE)      // 49152

__global__ void __launch_bounds__(128, 4)
gemm_lif(const float* __restrict__ bias, float* __restrict__ out, int M) {
    extern __shared__ char smem[];
    const u32 sb = smem_u32(smem);
    const int tid = threadIdx.x;
    const int n0 = blockIdx.x * BN;     // n fastest -> A tile shared in L2 by 4 CTAs
    const int m0 = blockIdx.y * BM;

    // loaders (128 threads), straight k-major layouts (no swizzle needed):
    // A: 512 units, 4/thread: row (tid>>4)+8r, unit tid&15   (rows 256B)
    // B: 1024 units, 8/thread: row (tid>>5)+4r, unit tid&31  (rows 512B)
    const u32 adst = (tid >> 4) * 256 + (tid & 15) * 16;
    const u32 bdst = A_ST + (tid >> 5) * 512 + (tid & 31) * 16;
    const float* ai = g_xt + (size_t)(tid >> 4) * M + m0 + (tid & 15) * 4;
    const float* bi = g_wt + (size_t)(tid >> 5) * ND + n0 + (tid & 31) * 4;

    const int NCHUNK = KD / BK;                  // 16

    // prologue: stage 0
    {
#pragma unroll
        for (int r = 0; r < 4; r++)
            cpa16(sb + adst + r * 2048, ai + (size_t)(8 * r) * M);
#pragma unroll
        for (int r = 0; r < 8; r++)
            cpa16(sb + bdst + r * 2048, bi + (size_t)(4 * r) * ND);
        CP_COMMIT();
        ai += (size_t)BK * M;
        bi += (size_t)BK * ND;
    }

    ull acc[4][8];
#pragma unroll
    for (int i = 0; i < 4; i++)
#pragma unroll
        for (int j = 0; j < 8; j++) acc[i][j] = 0ull;

    const int ty = tid >> 4;            // m: 8 x 8 = 64
    const int tx = tid & 15;            // n: 16 x 8 = 128

    for (int c = 0; c < NCHUNK; c++) {
        CP_WAIT0();
        __syncthreads();

        // issue chunk c+1 into the other buffer (its readers synced above)
        if (c + 1 < NCHUNK) {
            u32 s = sb + ((c + 1) & 1) * STAGE;
#pragma unroll
            for (int r = 0; r < 4; r++)
                cpa16(s + adst + r * 2048, ai + (size_t)(8 * r) * M);
#pragma unroll
            for (int r = 0; r < 8; r++)
                cpa16(s + bdst + r * 2048, bi + (size_t)(4 * r) * ND);
            CP_COMMIT();
            ai += (size_t)BK * M;
            bi += (size_t)BK * ND;
        }

        const char* st = smem + (c & 1) * STAGE;
#pragma unroll
        for (int k = 0; k < BK; k++) {
            union { float4 v; ull u[2]; } a0, a1;
            a0.v = *reinterpret_cast<const float4*>(st + k * 256 + ty * 32);
            a1.v = *reinterpret_cast<const float4*>(st + k * 256 + ty * 32 + 16);
            ull ap[4] = { a0.u[0], a0.u[1], a1.u[0], a1.u[1] };

            const char* brow = st + A_ST + k * 512 + tx * 32;
            float4 b0 = *reinterpret_cast<const float4*>(brow);
            float4 b1 = *reinterpret_cast<const float4*>(brow + 16);
            ull bp[8] = { pack_dup(b0.x), pack_dup(b0.y), pack_dup(b0.z), pack_dup(b0.w),
                          pack_dup(b1.x), pack_dup(b1.y), pack_dup(b1.z), pack_dup(b1.w) };

#pragma unroll
            for (int i = 0; i < 4; i++)
#pragma unroll
                for (int j = 0; j < 8; j++)
                    ffma2(acc[i][j], ap[i], bp[j]);
        }
    }

    // ---- epilogue: bias + LIF + store ----
    float4 bq0 = *reinterpret_cast<const float4*>(bias + n0 + tx * 8);
    float4 bq1 = *reinterpret_cast<const float4*>(bias + n0 + tx * 8 + 4);
    const float bv[8] = { bq0.x, bq0.y, bq0.z, bq0.w, bq1.x, bq1.y, bq1.z, bq1.w };

#pragma unroll
    for (int i = 0; i < 4; i++) {
        float lo[8], hi[8];
#pragma unroll
        for (int j = 0; j < 8; j++) unpack2(acc[i][j], lo[j], hi[j]);

        int m_lo = m0 + ty * 8 + 2 * i;
        float* p0 = out + (size_t)m_lo * ND + n0 + tx * 8;
        float* p1 = p0 + ND;

        float4 o;
        o.x = lif16(lo[0] + bv[0]); o.y = lif16(lo[1] + bv[1]);
        o.z = lif16(lo[2] + bv[2]); o.w = lif16(lo[3] + bv[3]);
        *reinterpret_cast<float4*>(p0) = o;
        o.x = lif16(lo[4] + bv[4]); o.y = lif16(lo[5] + bv[5]);
        o.z = lif16(lo[6] + bv[6]); o.w = lif16(lo[7] + bv[7]);
        *reinterpret_cast<float4*>(p0 + 4) = o;
        o.x = lif16(hi[0] + bv[0]); o.y = lif16(hi[1] + bv[1]);
        o.z = lif16(hi[2] + bv[2]); o.w = lif16(hi[3] + bv[3]);
        *reinterpret_cast<float4*>(p1) = o;
        o.x = lif16(hi[4] + bv[4]); o.y = lif16(hi[5] + bv[5]);
        o.z = lif16(hi[6] + bv[6]); o.w = lif16(hi[7] + bv[7]);
        *reinterpret_cast<float4*>(p1 + 4) = o;
    }
}

extern "C" void kernel_launch(void* const* d_in, const int* in_sizes, int n_in,
                              void* d_out, int out_size) {
    const float* x = (const float*)d_in[0];
    const float* W = (const float*)d_in[1];
    const float* b = (const float*)d_in[2];
    float* out = (float*)d_out;

    const int N = in_sizes[2];          // 512
    const int K = in_sizes[1] / N;      // 512
    const int M = in_sizes[0] / K;      // 32768

    dim3 tb(32, 8);
    dim3 tgx(K / 32, M / 32);
    transpose_x<<<tgx, tb>>>(x, M, K);
    dim3 tgw(K / 32, N / 32);
    transpose_w<<<tgw, tb>>>(W, N, K);

    cudaFuncSetAttribute(gemm_lif, cudaFuncAttributeMaxDynamicSharedMemorySize, SM_TOTAL);
    dim3 grid(N / BN, M / BM);
    gemm_lif<<<grid, 128, SM_TOTAL>>>(b, out, M);
}

// round 16
// speedup vs baseline: 1.8406x; 1.0603x over previous
#include <cuda_runtime.h>
#include <cstdint>

// ============================================================
// RSNN: out = LIF16(x @ W^T + b)/16,  M=32768, N=512, K=512 fp32
// Bit-exact fp32 GEMM (k-sequential FMA == reference rounding) on
// the FFMA2 pipe. R16: closed-form LIF epilogue — spike count is
// floor(16/tau(cur)); the 7 fp32 thresholds of tau are bisected on
// device with the identical fmaf step, so results are bit-equal to
// the 16-step loop (which matched the reference exactly).
// ============================================================

typedef unsigned int u32;
typedef unsigned long long ull;

#define KD 512
#define ND 512
#define MAXM 32768

__device__ float g_xt[(size_t)KD * MAXM];       // 64 MB  XT[k][m]
__device__ float g_wt[(size_t)KD * ND];         // 1 MB   WT[k][n]
__device__ float g_thr[7];                      // LIF count thresholds

__device__ __forceinline__ u32 smem_u32(const void* p) {
    u32 a;
    asm("{ .reg .u64 t; cvta.to.shared.u64 t, %1; cvt.u32.u64 %0, t; }" : "=r"(a) : "l"(p));
    return a;
}
__device__ __forceinline__ void cpa16(u32 dst, const float* src) {
    asm volatile("cp.async.cg.shared.global [%0], [%1], 16;" :: "r"(dst), "l"(src));
}
#define CP_COMMIT()  asm volatile("cp.async.commit_group;" ::: "memory")
#define CP_WAIT0()   asm volatile("cp.async.wait_group 0;" ::: "memory")

__device__ __forceinline__ void ffma2(ull& d, ull a, ull b) {
    asm("fma.rn.f32x2 %0, %1, %2, %3;" : "=l"(d) : "l"(a), "l"(b), "l"(d));
}
__device__ __forceinline__ ull pack_dup(float x) {
    ull r;
    u32 u = __float_as_uint(x);
    asm("mov.b64 %0, {%1, %1};" : "=l"(r) : "r"(u));
    return r;
}
__device__ __forceinline__ void unpack2(ull v, float& lo, float& hi) {
    u32 l, h;
    asm("mov.b64 {%0, %1}, %2;" : "=r"(l), "=r"(h) : "l"(v));
    lo = __uint_as_float(l);
    hi = __uint_as_float(h);
}

// ---------------- threshold init: bisect exact fp32 boundaries ----------------
// c[i] = min fp32 cur whose (un-reset) trajectory v<-fmaf(cur-v,0.5,v) from 0
// reaches >=1 within t steps, t in {1,2,3,4,5,8,16}. Trajectory is monotone in
// cur (rounded midpoint map), so bisection over positive-float bit patterns is
// exact. Spike count = (cur>=c1)*8+(cur>=c2)*3+(c3)+(c4)+(c5)+(c8)+(c16).
__global__ void init_thr() {
    const int tt[7] = {1, 2, 3, 4, 5, 8, 16};
    int i = threadIdx.x;
    if (i >= 7) return;
    int t = tt[i];
    u32 lo = __float_as_uint(1.0f);   // never spikes (v_t = 1-2^-t < 1)
    u32 hi = __float_as_uint(4.0f);   // spikes at step 1 (v1 = 2)
    while (hi - lo > 1) {
        u32 mid = (lo + hi) >> 1;
        float cur = __uint_as_float(mid);
        float v = 0.0f;
        for (int s = 0; s < t; s++) v = fmaf(cur - v, 0.5f, v);
        if (v >= 1.0f) hi = mid; else lo = mid;
    }
    g_thr[i] = __uint_as_float(hi);
}

// closed-form LIF16 (counts/16), using preloaded thresholds
__device__ __forceinline__ float lif_fast(float cur, const float* c) {
    float cnt = (cur >= c[0]) ? 8.0f : 0.0f;
    cnt += (cur >= c[1]) ? 3.0f : 0.0f;
    cnt += (cur >= c[2]) ? 1.0f : 0.0f;
    cnt += (cur >= c[3]) ? 1.0f : 0.0f;
    cnt += (cur >= c[4]) ? 1.0f : 0.0f;
    cnt += (cur >= c[5]) ? 1.0f : 0.0f;
    cnt += (cur >= c[6]) ? 1.0f : 0.0f;
    return cnt * 0.0625f;
}

// ---------------- pre-pass 1: XT[k][m] = X[m][k] ----------------
__global__ void transpose_x(const float* __restrict__ X, int M, int K) {
    __shared__ float t[32][33];
    const int kb = blockIdx.x * 32, mb = blockIdx.y * 32;
    const int tx = threadIdx.x, ty = threadIdx.y;   // 32 x 8
#pragma unroll
    for (int i = 0; i < 4; i++)
        t[ty + 8 * i][tx] = X[(size_t)(mb + ty + 8 * i) * K + kb + tx];
    __syncthreads();
#pragma unroll
    for (int i = 0; i < 4; i++)
        g_xt[(size_t)(kb + ty + 8 * i) * M + mb + tx] = t[tx][ty + 8 * i];
}

// ---------------- pre-pass 2: WT[k][n] = W[n][k] ----------------
__global__ void transpose_w(const float* __restrict__ W, int N, int K) {
    __shared__ float t[32][33];
    const int kb = blockIdx.x * 32, nb = blockIdx.y * 32;
    const int tx = threadIdx.x, ty = threadIdx.y;   // 32 x 8
#pragma unroll
    for (int i = 0; i < 4; i++)
        t[ty + 8 * i][tx] = W[(size_t)(nb + ty + 8 * i) * K + kb + tx];
    __syncthreads();
#pragma unroll
    for (int i = 0; i < 4; i++)
        g_wt[(size_t)(kb + ty + 8 * i) * N + nb + tx] = t[tx][ty + 8 * i];
}

// ---------------- GEMM + LIF ----------------
#define BM 64
#define BN 128
#define BK 32
#define NST 2
#define A_ST (BK * BM * 4)          // 8192  (A stage: [k][m], rows 256B)
#define B_ST (BK * BN * 4)          // 16384 (B stage: [k][n], rows 512B)
#define STAGE (A_ST + B_ST)         // 24576
#define SM_TOTAL (NST * STAGE)      // 49152

__global__ void __launch_bounds__(128, 4)
gemm_lif(const float* __restrict__ bias, float* __restrict__ out, int M) {
    extern __shared__ char smem[];
    const u32 sb = smem_u32(smem);
    const int tid = threadIdx.x;
    const int n0 = blockIdx.x * BN;     // n fastest -> A tile shared in L2 by 4 CTAs
    const int m0 = blockIdx.y * BM;

    // loaders (128 threads), straight k-major layouts:
    // A: 512 units, 4/thread: row (tid>>4)+8r ; B: 1024 units, 8/thread
    const u32 adst = (tid >> 4) * 256 + (tid & 15) * 16;
    const u32 bdst = A_ST + (tid >> 5) * 512 + (tid & 31) * 16;
    const float* ai = g_xt + (size_t)(tid >> 4) * M + m0 + (tid & 15) * 4;
    const float* bi = g_wt + (size_t)(tid >> 5) * ND + n0 + (tid & 31) * 4;

    const int NCHUNK = KD / BK;                  // 16

    // prologue: stage 0
    {
#pragma unroll
        for (int r = 0; r < 4; r++)
            cpa16(sb + adst + r * 2048, ai + (size_t)(8 * r) * M);
#pragma unroll
        for (int r = 0; r < 8; r++)
            cpa16(sb + bdst + r * 2048, bi + (size_t)(4 * r) * ND);
        CP_COMMIT();
        ai += (size_t)BK * M;
        bi += (size_t)BK * ND;
    }

    ull acc[4][8];
#pragma unroll
    for (int i = 0; i < 4; i++)
#pragma unroll
        for (int j = 0; j < 8; j++) acc[i][j] = 0ull;

    const int ty = tid >> 4;            // m: 8 x 8 = 64
    const int tx = tid & 15;            // n: 16 x 8 = 128

    for (int c = 0; c < NCHUNK; c++) {
        CP_WAIT0();
        __syncthreads();

        if (c + 1 < NCHUNK) {
            u32 s = sb + ((c + 1) & 1) * STAGE;
#pragma unroll
            for (int r = 0; r < 4; r++)
                cpa16(s + adst + r * 2048, ai + (size_t)(8 * r) * M);
#pragma unroll
            for (int r = 0; r < 8; r++)
                cpa16(s + bdst + r * 2048, bi + (size_t)(4 * r) * ND);
            CP_COMMIT();
            ai += (size_t)BK * M;
            bi += (size_t)BK * ND;
        }

        const char* st = smem + (c & 1) * STAGE;
#pragma unroll
        for (int k = 0; k < BK; k++) {
            union { float4 v; ull u[2]; } a0, a1;
            a0.v = *reinterpret_cast<const float4*>(st + k * 256 + ty * 32);
            a1.v = *reinterpret_cast<const float4*>(st + k * 256 + ty * 32 + 16);
            ull ap[4] = { a0.u[0], a0.u[1], a1.u[0], a1.u[1] };

            const char* brow = st + A_ST + k * 512 + tx * 32;
            float4 b0 = *reinterpret_cast<const float4*>(brow);
            float4 b1 = *reinterpret_cast<const float4*>(brow + 16);
            ull bp[8] = { pack_dup(b0.x), pack_dup(b0.y), pack_dup(b0.z), pack_dup(b0.w),
                          pack_dup(b1.x), pack_dup(b1.y), pack_dup(b1.z), pack_dup(b1.w) };

#pragma unroll
            for (int i = 0; i < 4; i++)
#pragma unroll
                for (int j = 0; j < 8; j++)
                    ffma2(acc[i][j], ap[i], bp[j]);
        }
    }

    // ---- epilogue: bias + closed-form LIF + store ----
    float thr[7];
#pragma unroll
    for (int i = 0; i < 7; i++) thr[i] = g_thr[i];

    float4 bq0 = *reinterpret_cast<const float4*>(bias + n0 + tx * 8);
    float4 bq1 = *reinterpret_cast<const float4*>(bias + n0 + tx * 8 + 4);
    const float bv[8] = { bq0.x, bq0.y, bq0.z, bq0.w, bq1.x, bq1.y, bq1.z, bq1.w };

#pragma unroll
    for (int i = 0; i < 4; i++) {
        float lo[8], hi[8];
#pragma unroll
        for (int j = 0; j < 8; j++) unpack2(acc[i][j], lo[j], hi[j]);

        int m_lo = m0 + ty * 8 + 2 * i;
        float* p0 = out + (size_t)m_lo * ND + n0 + tx * 8;
        float* p1 = p0 + ND;

        float4 o;
        o.x = lif_fast(lo[0] + bv[0], thr); o.y = lif_fast(lo[1] + bv[1], thr);
        o.z = lif_fast(lo[2] + bv[2], thr); o.w = lif_fast(lo[3] + bv[3], thr);
        *reinterpret_cast<float4*>(p0) = o;
        o.x = lif_fast(lo[4] + bv[4], thr); o.y = lif_fast(lo[5] + bv[5], thr);
        o.z = lif_fast(lo[6] + bv[6], thr); o.w = lif_fast(lo[7] + bv[7], thr);
        *reinterpret_cast<float4*>(p0 + 4) = o;
        o.x = lif_fast(hi[0] + bv[0], thr); o.y = lif_fast(hi[1] + bv[1], thr);
        o.z = lif_fast(hi[2] + bv[2], thr); o.w = lif_fast(hi[3] + bv[3], thr);
        *reinterpret_cast<float4*>(p1) = o;
        o.x = lif_fast(hi[4] + bv[4], thr); o.y = lif_fast(hi[5] + bv[5], thr);
        o.z = lif_fast(hi[6] + bv[6], thr); o.w = lif_fast(hi[7] + bv[7], thr);
        *reinterpret_cast<float4*>(p1 + 4) = o;
    }
}

extern "C" void kernel_launch(void* const* d_in, const int* in_sizes, int n_in,
                              void* d_out, int out_size) {
    const float* x = (const float*)d_in[0];
    const float* W = (const float*)d_in[1];
    const float* b = (const float*)d_in[2];
    float* out = (float*)d_out;

    const int N = in_sizes[2];          // 512
    const int K = in_sizes[1] / N;      // 512
    const int M = in_sizes[0] / K;      // 32768

    dim3 tb(32, 8);
    dim3 tgx(K / 32, M / 32);
    transpose_x<<<tgx, tb>>>(x, M, K);
    dim3 tgw(K / 32, N / 32);
    transpose_w<<<tgw, tb>>>(W, N, K);
    init_thr<<<1, 32>>>();

    cudaFuncSetAttribute(gemm_lif, cudaFuncAttributeMaxDynamicSharedMemorySize, SM_TOTAL);
    dim3 grid(N / BN, M / BM);
    gemm_lif<<<grid, 128, SM_TOTAL>>>(b, out, M);
}